// round 3
// baseline (speedup 1.0000x reference)
#include <cuda_runtime.h>
#include <math.h>
#include <stdint.h>

// Problem constants
#define BSZ 256
#define RR  196
#define TT  26
#define DD  512
#define AVN 3000
#define BT  (BSZ*TT)   // 6656

// ---------------- scratch layout ----------------
constexpr size_t N_SIMG      = (size_t)BSZ*DD;
constexpr size_t N_IMGSUM    = (size_t)BSZ*DD;
constexpr size_t N_X         = (size_t)BT*DD;
constexpr size_t N_WORDSUM   = (size_t)BSZ*DD;
constexpr size_t N_WCOMB     = (size_t)DD*2560;
constexpr size_t N_Y         = (size_t)BT*3584;
constexpr size_t N_PHRASE    = (size_t)BT*DD;
constexpr size_t N_PHRASESUM = (size_t)BSZ*DD;
constexpr size_t N_WXP       = (size_t)DD*2048;
constexpr size_t N_WHP       = (size_t)DD*2048;
constexpr size_t N_BP        = 2048;
constexpr size_t N_XG        = (size_t)BT*2048;
constexpr size_t N_H0        = (size_t)BSZ*DD;
constexpr size_t N_H1        = (size_t)BSZ*DD;
constexpr size_t N_C         = (size_t)BSZ*DD;
constexpr size_t N_SENT      = (size_t)BSZ*DD;
constexpr size_t N_V1        = (size_t)BSZ*DD;
constexpr size_t N_HW        = (size_t)BSZ*DD;
constexpr size_t N_CAT       = (size_t)BSZ*1024;
constexpr size_t N_HP        = (size_t)BSZ*DD;
constexpr size_t N_HS        = (size_t)BSZ*DD;

constexpr size_t O_SIMG      = 0;
constexpr size_t O_IMGSUM    = O_SIMG + N_SIMG;
constexpr size_t O_X         = O_IMGSUM + N_IMGSUM;
constexpr size_t O_WORDSUM   = O_X + N_X;
constexpr size_t O_WCOMB     = O_WORDSUM + N_WORDSUM;
constexpr size_t O_Y         = O_WCOMB + N_WCOMB;
constexpr size_t O_PHRASE    = O_Y + N_Y;
constexpr size_t O_PHRASESUM = O_PHRASE + N_PHRASE;
constexpr size_t O_WXP       = O_PHRASESUM + N_PHRASESUM;
constexpr size_t O_WHP       = O_WXP + N_WXP;
constexpr size_t O_BP        = O_WHP + N_WHP;
constexpr size_t O_XG        = O_BP + N_BP;
constexpr size_t O_H0        = O_XG + N_XG;
constexpr size_t O_H1        = O_H0 + N_H0;
constexpr size_t O_C         = O_H1 + N_H1;
constexpr size_t O_SENT      = O_C + N_C;
constexpr size_t O_V1        = O_SENT + N_SENT;
constexpr size_t O_HW        = O_V1 + N_V1;
constexpr size_t O_CAT       = O_HW + N_HW;
constexpr size_t O_HP        = O_CAT + N_CAT;
constexpr size_t O_HS        = O_HP + N_HP;
constexpr size_t SCRATCH_FLOATS = O_HS + N_HS;

__device__ float g_scratch[SCRATCH_FLOATS];

__device__ __forceinline__ float sigmoidf_(float x) { return 1.f / (1.f + __expf(-x)); }

// ---------------- small kernels ----------------

__global__ void reduce_img(const float* __restrict__ img, float* __restrict__ out) {
    int b = blockIdx.x, d = threadIdx.x;
    const float* p = img + (size_t)b * RR * DD + d;
    float s = 0.f;
#pragma unroll 4
    for (int r = 0; r < RR; ++r) s += p[(size_t)r * DD];
    out[b * DD + d] = s;
}

__global__ void gather_word(const int* __restrict__ q, const float* __restrict__ emb,
                            float* __restrict__ X) {
    int row = blockIdx.x, d = threadIdx.x;
    int tok = q[row];
    X[(size_t)row * DD + d] = emb[(size_t)tok * DD + d];
}

__global__ void reduce26(const float* __restrict__ src, float* __restrict__ dst) {
    int b = blockIdx.x, d = threadIdx.x;
    float s = 0.f;
#pragma unroll
    for (int t = 0; t < TT; ++t) s += src[((size_t)b * TT + t) * DD + d];
    dst[b * DD + d] = s;
}

// Wcomb[512][2560]: blk0 uni | blk1 bi-center | blk2 tri-center | blk3 tri-next | blk4 tri-prev
__global__ void build_wcomb5(const float* __restrict__ Wu, const float* __restrict__ Wb,
                             const float* __restrict__ Wt, float* __restrict__ Wc) {
    int idx = blockIdx.x * 256 + threadIdx.x;           // 512*2560 total
    int k = idx / 2560, n = idx % 2560;
    int blk = n >> 9, d = n & 511;
    float v;
    if (blk == 0)      v = Wu[k * 512 + d];
    else if (blk == 1) v = Wb[(256 + k) * 512 + d];
    else if (blk == 2) v = Wt[(512 + k) * 512 + d];
    else if (blk == 3) v = Wt[k * 512 + d];
    else               v = Wt[(1024 + k) * 512 + d];
    Wc[idx] = v;
}

// gate-interleave permute: Wp[k][4d+g] = W[k][g*512+d]   (W: [512][2048])
__global__ void permute_gates(const float* __restrict__ W, float* __restrict__ Wp) {
    int idx = blockIdx.x * 256 + threadIdx.x;           // 512*2048
    int k = idx >> 11, col = idx & 2047;
    int d = col >> 2, g = col & 3;
    Wp[idx] = W[(size_t)k * 2048 + g * 512 + d];
}

__global__ void permute_bias(const float* __restrict__ b, float* __restrict__ bp) {
    int col = blockIdx.x * 256 + threadIdx.x;           // 2048
    bp[col] = b[(col & 3) * 512 + (col >> 2)];
}

// phrase = max(uni, bi, tri). Y row layout (stride 3584):
// [0:512) uni | [512:1024) bi_c | [1024:1536) tri_c | [1536:2048) tri_next
// [2048:2560) tri_prev | [2560:3072) bi_next | [3072:3584) bi_prev
__global__ void combine_phrase(const float* __restrict__ Y,
                               const float* __restrict__ b_uni,
                               const float* __restrict__ b_bi,
                               const float* __restrict__ b_tri,
                               float* __restrict__ phrase) {
    int row = blockIdx.x, d = threadIdx.x;
    int t = row % TT;
    const float* y = Y + (size_t)row * 3584;
    float u  = y[d] + b_uni[d];
    float bi = y[512 + d] + b_bi[d];
    float tr = y[1024 + d] + b_tri[d];
    if (t > 0) {
        const float* yp = Y + (size_t)(row - 1) * 3584;
        bi += yp[2560 + d];
        tr += yp[1536 + d];
    }
    if (t < TT - 1) {
        const float* yn = Y + (size_t)(row + 1) * 3584;
        bi += yn[3072 + d];
        tr += yn[2048 + d];
    }
    phrase[(size_t)row * DD + d] = fmaxf(u, fmaxf(bi, tr));
}

// LSTM t=0: gates come straight from XGp (interleaved i,f,c,o per d)
__global__ void lstm0(const float* __restrict__ XGp, float* __restrict__ h0,
                      float* __restrict__ c, float* __restrict__ sent) {
    int b = blockIdx.x, d = threadIdx.x;
    float4 g = *(const float4*)&XGp[(size_t)b * TT * 2048 + 4 * d];
    float cn = sigmoidf_(g.x) * tanhf(g.z);
    float hn = sigmoidf_(g.w) * tanhf(cn);
    c[b * DD + d] = cn;
    h0[b * DD + d] = hn;
    sent[b * DD + d] = hn;
}

__global__ void ew_add(const float* __restrict__ a, const float* __restrict__ b,
                       float* __restrict__ o) {
    int i = blockIdx.x * 256 + threadIdx.x;
    o[i] = a[i] + b[i];
}

__global__ void ew_cat(const float* __restrict__ a, const float* __restrict__ b,
                       const float* __restrict__ h2, float* __restrict__ o) {
    int bb = blockIdx.x, d = threadIdx.x;
    o[(size_t)bb * 1024 + d]       = a[bb * DD + d] + b[bb * DD + d];
    o[(size_t)bb * 1024 + 512 + d] = h2[bb * DD + d];
}

// ---------------- GEMM: 128x128x8, double-buffered smem, 8x8/thread ----------------
// C[M,N](ldc) = A[M,K](lda) @ B[K,N](ldb) (+bias). M,N multiples of 128; K mult of 8.
__global__ __launch_bounds__(256) void sgemm128db(
    const float* __restrict__ A, int lda,
    const float* __restrict__ B, int ldb,
    float* __restrict__ C, int ldc,
    int M, int N, int K, const float* __restrict__ bias)
{
    __shared__ float As[2][8][128];
    __shared__ float Bs[2][8][128];
    int tid = threadIdx.x;
    int m0 = blockIdx.y * 128;
    int n0 = blockIdx.x * 128;
    int tx = tid & 15, ty = tid >> 4;

    int ar = tid >> 1;            // 0..127
    int ak = (tid & 1) * 4;       // 0 or 4
    int bk = tid >> 5;            // 0..7
    int bn = (tid & 31) * 4;      // 0..124

    const float* Aptr = A + (size_t)(m0 + ar) * lda + ak;
    const float* Bptr = B + (size_t)bk * ldb + n0 + bn;

    float4 aReg = *(const float4*)Aptr;
    float4 bReg = *(const float4*)Bptr;

    float acc[8][8];
#pragma unroll
    for (int i = 0; i < 8; i++)
#pragma unroll
        for (int j = 0; j < 8; j++) acc[i][j] = 0.f;

    // stage 0 into buffer 0
    As[0][ak + 0][ar] = aReg.x; As[0][ak + 1][ar] = aReg.y;
    As[0][ak + 2][ar] = aReg.z; As[0][ak + 3][ar] = aReg.w;
    *(float4*)&Bs[0][bk][bn] = bReg;
    __syncthreads();

    int nk = K >> 3;
    for (int kt = 0; kt < nk; ++kt) {
        if (kt + 1 < nk) {
            aReg = *(const float4*)(Aptr + (kt + 1) * 8);
            bReg = *(const float4*)(Bptr + (size_t)(kt + 1) * 8 * ldb);
        }
        int bf = kt & 1;
#pragma unroll
        for (int kk = 0; kk < 8; ++kk) {
            float4 a0 = *(const float4*)&As[bf][kk][ty * 4];
            float4 a1 = *(const float4*)&As[bf][kk][64 + ty * 4];
            float4 b0 = *(const float4*)&Bs[bf][kk][tx * 4];
            float4 b1 = *(const float4*)&Bs[bf][kk][64 + tx * 4];
            float av[8] = {a0.x, a0.y, a0.z, a0.w, a1.x, a1.y, a1.z, a1.w};
            float bv[8] = {b0.x, b0.y, b0.z, b0.w, b1.x, b1.y, b1.z, b1.w};
#pragma unroll
            for (int i = 0; i < 8; i++)
#pragma unroll
                for (int j = 0; j < 8; j++) acc[i][j] += av[i] * bv[j];
        }
        if (kt + 1 < nk) {
            int nb = (kt + 1) & 1;
            As[nb][ak + 0][ar] = aReg.x; As[nb][ak + 1][ar] = aReg.y;
            As[nb][ak + 2][ar] = aReg.z; As[nb][ak + 3][ar] = aReg.w;
            *(float4*)&Bs[nb][bk][bn] = bReg;
            __syncthreads();
        }
    }

#pragma unroll
    for (int qi = 0; qi < 2; ++qi)
#pragma unroll
        for (int i = 0; i < 4; ++i) {
            int row = m0 + qi * 64 + ty * 4 + i;
#pragma unroll
            for (int qj = 0; qj < 2; ++qj) {
                int col = n0 + qj * 64 + tx * 4;
                float4 v;
                v.x = acc[qi * 4 + i][qj * 4 + 0];
                v.y = acc[qi * 4 + i][qj * 4 + 1];
                v.z = acc[qi * 4 + i][qj * 4 + 2];
                v.w = acc[qi * 4 + i][qj * 4 + 3];
                if (bias) {
                    v.x += bias[col + 0]; v.y += bias[col + 1];
                    v.z += bias[col + 2]; v.w += bias[col + 3];
                }
                *(float4*)&C[(size_t)row * ldc + col] = v;
            }
        }
}

// ---------------- fused LSTM step: G = h@Whp (+XGp), gates, c/h/sent update ----------
// [256 x 2048] = [256 x 512] @ [512 x 2048]; 64x64 tiles; gate-interleaved columns.
__global__ __launch_bounds__(256) void lstm_step(
    const float* __restrict__ hin, const float* __restrict__ Whp,
    const float* __restrict__ XGp, int t,
    float* __restrict__ hout, float* __restrict__ c, float* __restrict__ sent)
{
    __shared__ float As[2][8][64];
    __shared__ float Bs[2][8][64];
    int tid = threadIdx.x;
    int m0 = blockIdx.y * 64;
    int n0 = blockIdx.x * 64;
    int tx = tid & 15, ty = tid >> 4;

    bool isA = tid < 128;
    int ar = tid >> 1;
    int ak = (tid & 1) * 4;
    int u  = tid - 128;
    int bk = u >> 4;
    int bn = (u & 15) * 4;

    const float* Aptr = hin + (size_t)(m0 + (isA ? ar : 0)) * DD + (isA ? ak : 0);
    const float* Bptr = Whp + (size_t)bk * 2048 + n0 + bn;

    float4 aReg = make_float4(0.f, 0.f, 0.f, 0.f);
    float4 bReg = make_float4(0.f, 0.f, 0.f, 0.f);
    if (isA) aReg = *(const float4*)Aptr; else bReg = *(const float4*)Bptr;

    float acc[4][4];
#pragma unroll
    for (int i = 0; i < 4; i++)
#pragma unroll
        for (int j = 0; j < 4; j++) acc[i][j] = 0.f;

    if (isA) {
        As[0][ak + 0][ar] = aReg.x; As[0][ak + 1][ar] = aReg.y;
        As[0][ak + 2][ar] = aReg.z; As[0][ak + 3][ar] = aReg.w;
    } else {
        *(float4*)&Bs[0][bk][bn] = bReg;
    }
    __syncthreads();

    const int nk = DD / 8;  // 64
    for (int kt = 0; kt < nk; ++kt) {
        if (kt + 1 < nk) {
            if (isA) aReg = *(const float4*)(Aptr + (kt + 1) * 8);
            else     bReg = *(const float4*)(Bptr + (size_t)(kt + 1) * 8 * 2048);
        }
        int bf = kt & 1;
#pragma unroll
        for (int kk = 0; kk < 8; ++kk) {
            float4 a   = *(const float4*)&As[bf][kk][ty * 4];
            float4 bv4 = *(const float4*)&Bs[bf][kk][tx * 4];
            float av[4] = {a.x, a.y, a.z, a.w};
            float bv[4] = {bv4.x, bv4.y, bv4.z, bv4.w};
#pragma unroll
            for (int i = 0; i < 4; i++)
#pragma unroll
                for (int j = 0; j < 4; j++) acc[i][j] += av[i] * bv[j];
        }
        if (kt + 1 < nk) {
            int nb = (kt + 1) & 1;
            if (isA) {
                As[nb][ak + 0][ar] = aReg.x; As[nb][ak + 1][ar] = aReg.y;
                As[nb][ak + 2][ar] = aReg.z; As[nb][ak + 3][ar] = aReg.w;
            } else {
                *(float4*)&Bs[nb][bk][bn] = bReg;
            }
            __syncthreads();
        }
    }

    // epilogue: each thread owns hidden unit d = n0/4 + tx, rows m0+ty*4+i
    int d = (n0 >> 2) + tx;
#pragma unroll
    for (int i = 0; i < 4; i++) {
        int row = m0 + ty * 4 + i;
        float4 g4 = *(const float4*)&XGp[((size_t)row * TT + t) * 2048 + 4 * d];
        float iv = acc[i][0] + g4.x;
        float fv = acc[i][1] + g4.y;
        float cg = acc[i][2] + g4.z;
        float ov = acc[i][3] + g4.w;
        float cp = c[row * DD + d];
        float cn = sigmoidf_(fv) * cp + sigmoidf_(iv) * tanhf(cg);
        float hn = sigmoidf_(ov) * tanhf(cn);
        c[row * DD + d] = cn;
        hout[row * DD + d] = hn;
        sent[row * DD + d] += hn;
    }
}

// ---------------- GEMM: 64x64x8, flexible epilogue (heads / classifier) -------------
__global__ __launch_bounds__(256) void sgemm64(
    const float* __restrict__ A, const float* __restrict__ B, float* __restrict__ C,
    int M, int N, int K,
    const float* __restrict__ bias, float biasScale, int act)
{
    __shared__ float As[8][64];
    __shared__ float Bs[8][64];
    int tid = threadIdx.x;
    int m0 = blockIdx.y * 64;
    int n0 = blockIdx.x * 64;
    int tx = tid & 15, ty = tid >> 4;

    bool isA = tid < 128;
    int ar = tid >> 1;
    int ak = (tid & 1) * 4;
    int u  = tid - 128;
    int bk = u >> 4;
    int bn = (u & 15) * 4;

    const float* Aptr = A + (size_t)(m0 + (isA ? ar : 0)) * K + (isA ? ak : 0);
    int bcol = n0 + bn;
    const float* Bptr = B + (size_t)bk * N + bcol;

    float4 aReg = make_float4(0.f, 0.f, 0.f, 0.f);
    float4 bReg = make_float4(0.f, 0.f, 0.f, 0.f);
    if (isA) aReg = *(const float4*)Aptr;
    else {
        if (bcol + 3 < N) bReg = *(const float4*)Bptr;
        else {
            bReg.x = (bcol + 0 < N) ? Bptr[0] : 0.f;
            bReg.y = (bcol + 1 < N) ? Bptr[1] : 0.f;
            bReg.z = (bcol + 2 < N) ? Bptr[2] : 0.f;
            bReg.w = (bcol + 3 < N) ? Bptr[3] : 0.f;
        }
    }

    float acc[4][4];
#pragma unroll
    for (int i = 0; i < 4; i++)
#pragma unroll
        for (int j = 0; j < 4; j++) acc[i][j] = 0.f;

    int nk = K >> 3;
    for (int kt = 0; kt < nk; ++kt) {
        if (isA) {
            As[ak + 0][ar] = aReg.x; As[ak + 1][ar] = aReg.y;
            As[ak + 2][ar] = aReg.z; As[ak + 3][ar] = aReg.w;
        } else {
            *(float4*)&Bs[bk][bn] = bReg;
        }
        __syncthreads();
        if (kt + 1 < nk) {
            if (isA) aReg = *(const float4*)(Aptr + (kt + 1) * 8);
            else {
                const float* bp = Bptr + (size_t)(kt + 1) * 8 * N;
                if (bcol + 3 < N) bReg = *(const float4*)bp;
                else {
                    bReg.x = (bcol + 0 < N) ? bp[0] : 0.f;
                    bReg.y = (bcol + 1 < N) ? bp[1] : 0.f;
                    bReg.z = (bcol + 2 < N) ? bp[2] : 0.f;
                    bReg.w = (bcol + 3 < N) ? bp[3] : 0.f;
                }
            }
        }
#pragma unroll
        for (int kk = 0; kk < 8; ++kk) {
            float4 a = *(const float4*)&As[kk][ty * 4];
            float4 bv4 = *(const float4*)&Bs[kk][tx * 4];
            float av[4] = {a.x, a.y, a.z, a.w};
            float bv[4] = {bv4.x, bv4.y, bv4.z, bv4.w};
#pragma unroll
            for (int i = 0; i < 4; i++)
#pragma unroll
                for (int j = 0; j < 4; j++) acc[i][j] += av[i] * bv[j];
        }
        __syncthreads();
    }

#pragma unroll
    for (int i = 0; i < 4; i++) {
        int row = m0 + ty * 4 + i;
#pragma unroll
        for (int j = 0; j < 4; j++) {
            int col = n0 + tx * 4 + j;
            if (col >= N) continue;
            float v = acc[i][j];
            if (bias) v += bias[col] * biasScale;
            if (act)  v = tanhf(v);
            C[(size_t)row * N + col] = v;
        }
    }
}

// ---------------- launch ----------------
extern "C" void kernel_launch(void* const* d_in, const int* in_sizes, int n_in,
                              void* d_out, int out_size) {
    const float* image_feat = (const float*)d_in[0];
    const int*   qenc       = (const int*)d_in[1];
    const float* W_ip   = (const float*)d_in[2];
    const float* b_ip   = (const float*)d_in[3];
    const float* emb    = (const float*)d_in[4];
    const float* W_uni  = (const float*)d_in[5];
    const float* b_uni  = (const float*)d_in[6];
    const float* W_bi   = (const float*)d_in[7];
    const float* b_bi   = (const float*)d_in[8];
    const float* W_tri  = (const float*)d_in[9];
    const float* b_tri  = (const float*)d_in[10];
    const float* Wx     = (const float*)d_in[11];
    const float* Wh     = (const float*)d_in[12];
    const float* b_lstm = (const float*)d_in[13];
    // d_in[14..23]: affinity/attention weights — dead (softmax over 1 logit == 1)
    const float* W_w    = (const float*)d_in[24];
    const float* b_w    = (const float*)d_in[25];
    const float* W_p    = (const float*)d_in[26];
    const float* b_p    = (const float*)d_in[27];
    const float* W_s    = (const float*)d_in[28];
    const float* b_s    = (const float*)d_in[29];
    const float* W_f    = (const float*)d_in[30];
    const float* b_f    = (const float*)d_in[31];
    float* out = (float*)d_out;

    float* S = nullptr;
    cudaGetSymbolAddress((void**)&S, g_scratch);
    float* Simg      = S + O_SIMG;
    float* imgsum    = S + O_IMGSUM;
    float* X         = S + O_X;
    float* wordsum   = S + O_WORDSUM;
    float* Wcomb     = S + O_WCOMB;
    float* Y         = S + O_Y;
    float* phrase    = S + O_PHRASE;
    float* phrasesum = S + O_PHRASESUM;
    float* Wxp       = S + O_WXP;
    float* Whp       = S + O_WHP;
    float* bp        = S + O_BP;
    float* XGp       = S + O_XG;
    float* h0        = S + O_H0;
    float* h1        = S + O_H1;
    float* c         = S + O_C;
    float* sentsum   = S + O_SENT;
    float* v1        = S + O_V1;
    float* hw        = S + O_HW;
    float* cat       = S + O_CAT;
    float* hp        = S + O_HP;
    float* hs        = S + O_HS;

    // image path
    reduce_img<<<BSZ, DD>>>(image_feat, Simg);
    sgemm64<<<dim3(8, 4), 256>>>(Simg, W_ip, imgsum, 256, 512, 512, b_ip, (float)RR, 0);

    // weight prep
    build_wcomb5<<<(512 * 2560) / 256, 256>>>(W_uni, W_bi, W_tri, Wcomb);
    permute_gates<<<(512 * 2048) / 256, 256>>>(Wx, Wxp);
    permute_gates<<<(512 * 2048) / 256, 256>>>(Wh, Whp);
    permute_bias<<<2048 / 256, 256>>>(b_lstm, bp);

    // word path
    gather_word<<<BT, DD>>>(qenc, emb, X);
    reduce26<<<BSZ, DD>>>(X, wordsum);

    // phrase: main 5-block GEMM + two half-K neighbor GEMMs + shifted combine
    sgemm128db<<<dim3(2560 / 128, BT / 128), 256>>>(X, 512, Wcomb, 2560, Y, 3584,
                                                    BT, 2560, 512, nullptr);
    // bi_next: sum_{k>=256} x[k]*Wb[k-256]  -> Y[:,2560:3072]
    sgemm128db<<<dim3(512 / 128, BT / 128), 256>>>(X + 256, 512, W_bi, 512, Y + 2560, 3584,
                                                   BT, 512, 256, nullptr);
    // bi_prev: sum_{k<256} x[k]*Wb[768+k]   -> Y[:,3072:3584]
    sgemm128db<<<dim3(512 / 128, BT / 128), 256>>>(X, 512, W_bi + 768 * 512, 512, Y + 3072, 3584,
                                                   BT, 512, 256, nullptr);
    combine_phrase<<<BT, DD>>>(Y, b_uni, b_bi, b_tri, phrase);
    reduce26<<<BSZ, DD>>>(phrase, phrasesum);

    // LSTM: precompute gate-interleaved x@Wxp + bp, then 26 fused recurrent steps
    sgemm128db<<<dim3(2048 / 128, BT / 128), 256>>>(phrase, 512, Wxp, 2048, XGp, 2048,
                                                    BT, 2048, 512, bp);
    lstm0<<<BSZ, DD>>>(XGp, h0, c, sentsum);
    for (int t = 1; t < TT; ++t) {
        const float* hin = (t & 1) ? h0 : h1;
        float*       ho  = (t & 1) ? h1 : h0;
        lstm_step<<<dim3(32, 4), 256>>>(hin, Whp, XGp, t, ho, c, sentsum);
    }

    // heads
    ew_add<<<(BSZ * DD) / 256, 256>>>(imgsum, wordsum, v1);
    sgemm64<<<dim3(8, 4), 256>>>(v1, W_w, hw, 256, 512, 512, b_w, 1.f, 1);
    ew_cat<<<BSZ, DD>>>(imgsum, phrasesum, hw, cat);
    sgemm64<<<dim3(8, 4), 256>>>(cat, W_p, hp, 256, 512, 1024, b_p, 1.f, 1);
    ew_cat<<<BSZ, DD>>>(imgsum, sentsum, hp, cat);
    sgemm64<<<dim3(8, 4), 256>>>(cat, W_s, hs, 256, 512, 1024, b_s, 1.f, 1);

    // final classifier
    sgemm64<<<dim3((AVN + 63) / 64, 4), 256>>>(hs, W_f, out, 256, AVN, 512, b_f, 1.f, 0);
}

// round 6
// speedup vs baseline: 1.2062x; 1.2062x over previous
#include <cuda_runtime.h>
#include <cuda_bf16.h>
#include <math.h>
#include <stdint.h>

// Problem constants
#define BSZ 256
#define RR  196
#define TT  26
#define DD  512
#define AVN 3000
#define BT  (BSZ*TT)   // 6656
#define NY  3584
#define NG  2048

// ---------------- fp32 scratch ----------------
constexpr size_t N_SIMG      = (size_t)BSZ*DD;
constexpr size_t N_IMGSUM    = (size_t)BSZ*DD;
constexpr size_t N_X         = (size_t)BT*DD;
constexpr size_t N_WORDSUM   = (size_t)BSZ*DD;
constexpr size_t N_Y         = (size_t)BT*NY;
constexpr size_t N_PHRASE    = (size_t)BT*DD;
constexpr size_t N_PHRASESUM = (size_t)BSZ*DD;
constexpr size_t N_WHP       = (size_t)DD*NG;
constexpr size_t N_BP        = NG;
constexpr size_t N_XG        = (size_t)BT*NG;
constexpr size_t N_H0        = (size_t)BSZ*DD;
constexpr size_t N_H1        = (size_t)BSZ*DD;
constexpr size_t N_C         = (size_t)BSZ*DD;
constexpr size_t N_SENT      = (size_t)BSZ*DD;
constexpr size_t N_V1        = (size_t)BSZ*DD;
constexpr size_t N_HW        = (size_t)BSZ*DD;
constexpr size_t N_CAT       = (size_t)BSZ*1024;
constexpr size_t N_HP        = (size_t)BSZ*DD;
constexpr size_t N_HS        = (size_t)BSZ*DD;

constexpr size_t O_SIMG      = 0;
constexpr size_t O_IMGSUM    = O_SIMG + N_SIMG;
constexpr size_t O_X         = O_IMGSUM + N_IMGSUM;
constexpr size_t O_WORDSUM   = O_X + N_X;
constexpr size_t O_Y         = O_WORDSUM + N_WORDSUM;
constexpr size_t O_PHRASE    = O_Y + N_Y;
constexpr size_t O_PHRASESUM = O_PHRASE + N_PHRASE;
constexpr size_t O_WHP       = O_PHRASESUM + N_PHRASESUM;
constexpr size_t O_BP        = O_WHP + N_WHP;
constexpr size_t O_XG        = O_BP + N_BP;
constexpr size_t O_H0        = O_XG + N_XG;
constexpr size_t O_H1        = O_H0 + N_H0;
constexpr size_t O_C         = O_H1 + N_H1;
constexpr size_t O_SENT      = O_C + N_C;
constexpr size_t O_V1        = O_SENT + N_SENT;
constexpr size_t O_HW        = O_V1 + N_V1;
constexpr size_t O_CAT       = O_HW + N_HW;
constexpr size_t O_HP        = O_CAT + N_CAT;
constexpr size_t O_HS        = O_HP + N_HP;
constexpr size_t SCRATCH_FLOATS = O_HS + N_HS;

__device__ float g_scratch[SCRATCH_FLOATS];

// bf16 split buffers
__device__ __nv_bfloat16 g_Xhi[(size_t)BT*DD];
__device__ __nv_bfloat16 g_Xlo[(size_t)BT*DD];
__device__ __nv_bfloat16 g_Phi[(size_t)BT*DD];
__device__ __nv_bfloat16 g_Plo[(size_t)BT*DD];
__device__ __nv_bfloat16 g_WcT_hi[(size_t)NY*DD];
__device__ __nv_bfloat16 g_WcT_lo[(size_t)NY*DD];
__device__ __nv_bfloat16 g_WxT_hi[(size_t)NG*DD];
__device__ __nv_bfloat16 g_WxT_lo[(size_t)NG*DD];

__device__ __forceinline__ float sigmoidf_(float x) { return 1.f / (1.f + __expf(-x)); }

__device__ __forceinline__ uint32_t smem_u32(const void* p) {
    uint32_t a;
    asm("{ .reg .u64 t; cvta.to.shared.u64 t, %1; cvt.u32.u64 %0, t; }" : "=r"(a) : "l"(p));
    return a;
}

// ---------------- mma.sync helpers (sm_80+ portable) ----------------
__device__ __forceinline__ void cp16(uint32_t sm, const void* g) {
    asm volatile("cp.async.cg.shared.global [%0], [%1], 16;" :: "r"(sm), "l"(g));
}
__device__ __forceinline__ void ldm_x4(uint32_t& r0, uint32_t& r1, uint32_t& r2, uint32_t& r3,
                                       uint32_t addr) {
    asm volatile("ldmatrix.sync.aligned.m8n8.x4.shared.b16 {%0,%1,%2,%3}, [%4];"
        : "=r"(r0), "=r"(r1), "=r"(r2), "=r"(r3) : "r"(addr));
}
__device__ __forceinline__ void mma16816(float* d, const uint32_t* a, uint32_t b0, uint32_t b1) {
    asm volatile("mma.sync.aligned.m16n8k16.row.col.f32.bf16.bf16.f32 "
        "{%0,%1,%2,%3}, {%4,%5,%6,%7}, {%8,%9}, {%0,%1,%2,%3};"
        : "+f"(d[0]), "+f"(d[1]), "+f"(d[2]), "+f"(d[3])
        : "r"(a[0]), "r"(a[1]), "r"(a[2]), "r"(a[3]), "r"(b0), "r"(b1));
}

// ---------------- TC GEMM via mma.sync: C[M x Nc] = A[M x 512] @ B[Nc x 512]^T (+bias) --
// Split precision as extended-K: 24 chunks of K=64; phase 0: Ahi*Bhi, 1: Ahi*Blo, 2: Alo*Bhi.
// CTA tile 128x128, 8 warps each 64x32. 2-stage cp.async pipeline.
// Dynamic smem 64KB: A[2][16KB] then B[2][16KB]; rows of 64 bf16 = 128B, XOR-swizzled 16B chunks.
#define MMA_SMEM_BYTES 65536
#define NCHUNK 24
__global__ __launch_bounds__(256) void mma_gemm(
    const __nv_bfloat16* __restrict__ Ahi, const __nv_bfloat16* __restrict__ Alo,
    const __nv_bfloat16* __restrict__ Bhi, const __nv_bfloat16* __restrict__ Blo,
    float* __restrict__ C, int ldc, const float* __restrict__ bias)
{
    extern __shared__ __align__(1024) uint8_t dsm[];
    uint32_t sbase = smem_u32(dsm);
    int tid = threadIdx.x;
    int wid = tid >> 5, lid = tid & 31;
    int m0 = blockIdx.y * 128;
    int n0 = blockIdx.x * 128;
    int wm = wid >> 2;          // 0..1 : rows wm*64
    int wn = wid & 3;           // 0..3 : cols wn*32

    float acc[4][4][4];
#pragma unroll
    for (int mi = 0; mi < 4; ++mi)
#pragma unroll
        for (int ni = 0; ni < 4; ++ni)
#pragma unroll
            for (int k = 0; k < 4; ++k) acc[mi][ni][k] = 0.f;

    // cp.async mapping: thread -> row r (0..127), 4 consecutive 16B chunks
    int r = tid >> 1;
    int cb = (tid & 1) * 4;
    int rsw = r & 7;

    auto load_chunk = [&](int cc, int buf) {
        int phase = cc >> 3;
        int k0 = (cc & 7) << 6;
        const __nv_bfloat16* As = (phase == 2) ? Alo : Ahi;
        const __nv_bfloat16* Bs = (phase == 1) ? Blo : Bhi;
        const __nv_bfloat16* ga = As + (size_t)(m0 + r) * DD + k0;
        const __nv_bfloat16* gb = Bs + (size_t)(n0 + r) * DD + k0;
        uint32_t sa = sbase + buf * 16384 + r * 128;
        uint32_t sb = sbase + 32768 + buf * 16384 + r * 128;
#pragma unroll
        for (int i = 0; i < 4; ++i) {
            int c16 = cb + i;
            uint32_t sw = (uint32_t)((c16 ^ rsw) << 4);
            cp16(sa + sw, ga + c16 * 8);
            cp16(sb + sw, gb + c16 * 8);
        }
    };

    // ldmatrix lane routing
    int sub = lid >> 3;         // 0..3
    int lrow = lid & 7;
    int a_roff = (sub & 1) * 8 + lrow;   // row within 16-row frag
    int a_kc = sub >> 1;                 // 16B chunk within k16
    int b_noff = (sub >> 1) * 8 + lrow;  // n-row within 16-col group
    int b_kc = sub & 1;

    auto compute_chunk = [&](int buf) {
        uint32_t aB = sbase + buf * 16384;
        uint32_t bB = sbase + 32768 + buf * 16384;
#pragma unroll
        for (int kk = 0; kk < 4; ++kk) {
            uint32_t af[4][4];
#pragma unroll
            for (int mi = 0; mi < 4; ++mi) {
                int rr = wm * 64 + mi * 16 + a_roff;
                int c16 = kk * 2 + a_kc;
                ldm_x4(af[mi][0], af[mi][1], af[mi][2], af[mi][3],
                       aB + rr * 128 + ((c16 ^ (rr & 7)) << 4));
            }
            uint32_t bf[2][4];
#pragma unroll
            for (int nj = 0; nj < 2; ++nj) {
                int rr = wn * 32 + nj * 16 + b_noff;
                int c16 = kk * 2 + b_kc;
                ldm_x4(bf[nj][0], bf[nj][1], bf[nj][2], bf[nj][3],
                       bB + rr * 128 + ((c16 ^ (rr & 7)) << 4));
            }
#pragma unroll
            for (int mi = 0; mi < 4; ++mi)
#pragma unroll
                for (int ni = 0; ni < 4; ++ni)
                    mma16816(acc[mi][ni], af[mi],
                             bf[ni >> 1][(ni & 1) * 2 + 0],
                             bf[ni >> 1][(ni & 1) * 2 + 1]);
        }
    };

    load_chunk(0, 0);
    asm volatile("cp.async.commit_group;" ::: "memory");
    for (int cc = 0; cc < NCHUNK; ++cc) {
        if (cc + 1 < NCHUNK) {
            load_chunk(cc + 1, (cc + 1) & 1);
            asm volatile("cp.async.commit_group;" ::: "memory");
            asm volatile("cp.async.wait_group 1;" ::: "memory");
        } else {
            asm volatile("cp.async.wait_group 0;" ::: "memory");
        }
        __syncthreads();
        compute_chunk(cc & 1);
        __syncthreads();
    }

    // epilogue
    int grp = lid >> 2, q = lid & 3;
#pragma unroll
    for (int mi = 0; mi < 4; ++mi) {
        int row = m0 + wm * 64 + mi * 16 + grp;
#pragma unroll
        for (int ni = 0; ni < 4; ++ni) {
            int col = n0 + wn * 32 + ni * 8 + q * 2;
            float b0 = 0.f, b1 = 0.f;
            if (bias) { b0 = bias[col]; b1 = bias[col + 1]; }
            float2 v0 = make_float2(acc[mi][ni][0] + b0, acc[mi][ni][1] + b1);
            float2 v1 = make_float2(acc[mi][ni][2] + b0, acc[mi][ni][3] + b1);
            *(float2*)&C[(size_t)row * ldc + col] = v0;
            *(float2*)&C[(size_t)(row + 8) * ldc + col] = v1;
        }
    }
}

// ---------------- small kernels ----------------

__global__ void reduce_img(const float* __restrict__ img, float* __restrict__ out) {
    int b = blockIdx.x, d = threadIdx.x;
    const float* p = img + (size_t)b * RR * DD + d;
    float s = 0.f;
#pragma unroll 4
    for (int r = 0; r < RR; ++r) s += p[(size_t)r * DD];
    out[b * DD + d] = s;
}

__global__ void gather_word(const int* __restrict__ q, const float* __restrict__ emb,
                            float* __restrict__ X) {
    int row = blockIdx.x, d = threadIdx.x;
    int tok = q[row];
    X[(size_t)row * DD + d] = emb[(size_t)tok * DD + d];
}

__global__ void reduce26(const float* __restrict__ src, float* __restrict__ dst) {
    int b = blockIdx.x, d = threadIdx.x;
    float s = 0.f;
#pragma unroll
    for (int t = 0; t < TT; ++t) s += src[((size_t)b * TT + t) * DD + d];
    dst[b * DD + d] = s;
}

// split fp32 -> bf16 hi + bf16 residual
__global__ void split2(const float* __restrict__ x, __nv_bfloat16* __restrict__ hi,
                       __nv_bfloat16* __restrict__ lo) {
    size_t i = (size_t)blockIdx.x * 256 + threadIdx.x;
    float v = x[i];
    __nv_bfloat16 h = __float2bfloat16(v);
    hi[i] = h;
    lo[i] = __float2bfloat16(v - __bfloat162float(h));
}

// WcombT[n][k] (n<3584) transposed 7-block conv weight, split to bf16 hi/lo
// blk: 0 uni | 1 bi_c | 2 bi_next(k>=256) | 3 bi_prev(k<256) | 4 tri_c | 5 tri_next | 6 tri_prev
__global__ void build_wcombT(const float* __restrict__ Wu, const float* __restrict__ Wb,
                             const float* __restrict__ Wt,
                             __nv_bfloat16* __restrict__ hi, __nv_bfloat16* __restrict__ lo) {
    size_t idx = (size_t)blockIdx.x * 256 + threadIdx.x;    // NY*512
    int n = (int)(idx >> 9), k = (int)(idx & 511);
    int blk = n >> 9, d = n & 511;
    float v = 0.f;
    if (blk == 0)      v = Wu[k * 512 + d];
    else if (blk == 1) v = Wb[(256 + k) * 512 + d];
    else if (blk == 2) { if (k >= 256) v = Wb[(k - 256) * 512 + d]; }
    else if (blk == 3) { if (k < 256)  v = Wb[(768 + k) * 512 + d]; }
    else if (blk == 4) v = Wt[(512 + k) * 512 + d];
    else if (blk == 5) v = Wt[k * 512 + d];
    else               v = Wt[(1024 + k) * 512 + d];
    __nv_bfloat16 h = __float2bfloat16(v);
    hi[idx] = h;
    lo[idx] = __float2bfloat16(v - __bfloat162float(h));
}

// WxT[n][k]: gate-interleaved transposed LSTM input weight, n = 4d+g
__global__ void build_wxT(const float* __restrict__ Wx,
                          __nv_bfloat16* __restrict__ hi, __nv_bfloat16* __restrict__ lo) {
    size_t idx = (size_t)blockIdx.x * 256 + threadIdx.x;    // NG*512
    int n = (int)(idx >> 9), k = (int)(idx & 511);
    int d = n >> 2, g = n & 3;
    float v = Wx[(size_t)k * NG + g * 512 + d];
    __nv_bfloat16 h = __float2bfloat16(v);
    hi[idx] = h;
    lo[idx] = __float2bfloat16(v - __bfloat162float(h));
}

// gate-interleave permute for Wh (fp32, used by SIMT lstm_step)
__global__ void permute_gates(const float* __restrict__ W, float* __restrict__ Wp) {
    int idx = blockIdx.x * 256 + threadIdx.x;           // 512*2048
    int k = idx >> 11, col = idx & 2047;
    int d = col >> 2, g = col & 3;
    Wp[idx] = W[(size_t)k * NG + g * 512 + d];
}

__global__ void permute_bias(const float* __restrict__ b, float* __restrict__ bp) {
    int col = blockIdx.x * 256 + threadIdx.x;           // 2048
    bp[col] = b[(col & 3) * 512 + (col >> 2)];
}

// phrase = max(uni, bi, tri); Y layout: 7 blocks of 512 per row (validated round 2)
__global__ void combine_phrase(const float* __restrict__ Y,
                               const float* __restrict__ b_uni,
                               const float* __restrict__ b_bi,
                               const float* __restrict__ b_tri,
                               float* __restrict__ phrase) {
    int row = blockIdx.x, d = threadIdx.x;
    int t = row % TT;
    const float* y = Y + (size_t)row * NY;
    float u  = y[d] + b_uni[d];
    float bi = y[512 + d] + b_bi[d];
    if (t > 0)      bi += Y[(size_t)(row - 1) * NY + 1024 + d];
    if (t < TT - 1) bi += Y[(size_t)(row + 1) * NY + 1536 + d];
    float tr = y[2048 + d] + b_tri[d];
    if (t > 0)      tr += Y[(size_t)(row - 1) * NY + 2560 + d];
    if (t < TT - 1) tr += Y[(size_t)(row + 1) * NY + 3072 + d];
    phrase[(size_t)row * DD + d] = fmaxf(u, fmaxf(bi, tr));
}

// LSTM t=0: gates straight from XGp (interleaved i,f,c,o per d)
__global__ void lstm0(const float* __restrict__ XGp, float* __restrict__ h0,
                      float* __restrict__ c, float* __restrict__ sent) {
    int b = blockIdx.x, d = threadIdx.x;
    float4 g = *(const float4*)&XGp[(size_t)b * TT * NG + 4 * d];
    float cn = sigmoidf_(g.x) * tanhf(g.z);
    float hn = sigmoidf_(g.w) * tanhf(cn);
    c[b * DD + d] = cn;
    h0[b * DD + d] = hn;
    sent[b * DD + d] = hn;
}

__global__ void ew_add(const float* __restrict__ a, const float* __restrict__ b,
                       float* __restrict__ o) {
    int i = blockIdx.x * 256 + threadIdx.x;
    o[i] = a[i] + b[i];
}

__global__ void ew_cat(const float* __restrict__ a, const float* __restrict__ b,
                       const float* __restrict__ h2, float* __restrict__ o) {
    int bb = blockIdx.x, d = threadIdx.x;
    o[(size_t)bb * 1024 + d]       = a[bb * DD + d] + b[bb * DD + d];
    o[(size_t)bb * 1024 + 512 + d] = h2[bb * DD + d];
}

// ---------------- fused LSTM step (SIMT): G = h@Whp + XGp, cell update -------------
__global__ __launch_bounds__(256) void lstm_step(
    const float* __restrict__ hin, const float* __restrict__ Whp,
    const float* __restrict__ XGp, int t,
    float* __restrict__ hout, float* __restrict__ c, float* __restrict__ sent)
{
    __shared__ float As[2][8][64];
    __shared__ float Bs[2][8][64];
    int tid = threadIdx.x;
    int m0 = blockIdx.y * 64;
    int n0 = blockIdx.x * 64;
    int tx = tid & 15, ty = tid >> 4;

    bool isA = tid < 128;
    int ar = tid >> 1;
    int ak = (tid & 1) * 4;
    int u  = tid - 128;
    int bk = u >> 4;
    int bn = (u & 15) * 4;

    const float* Aptr = hin + (size_t)(m0 + (isA ? ar : 0)) * DD + (isA ? ak : 0);
    const float* Bptr = Whp + (size_t)bk * NG + n0 + bn;

    float4 aReg = make_float4(0.f, 0.f, 0.f, 0.f);
    float4 bReg = make_float4(0.f, 0.f, 0.f, 0.f);
    if (isA) aReg = *(const float4*)Aptr; else bReg = *(const float4*)Bptr;

    float acc[4][4];
#pragma unroll
    for (int i = 0; i < 4; i++)
#pragma unroll
        for (int j = 0; j < 4; j++) acc[i][j] = 0.f;

    if (isA) {
        As[0][ak + 0][ar] = aReg.x; As[0][ak + 1][ar] = aReg.y;
        As[0][ak + 2][ar] = aReg.z; As[0][ak + 3][ar] = aReg.w;
    } else {
        *(float4*)&Bs[0][bk][bn] = bReg;
    }
    __syncthreads();

    const int nk = DD / 8;
    for (int kt = 0; kt < nk; ++kt) {
        if (kt + 1 < nk) {
            if (isA) aReg = *(const float4*)(Aptr + (kt + 1) * 8);
            else     bReg = *(const float4*)(Bptr + (size_t)(kt + 1) * 8 * NG);
        }
        int bf = kt & 1;
#pragma unroll
        for (int kk = 0; kk < 8; ++kk) {
            float4 a   = *(const float4*)&As[bf][kk][ty * 4];
            float4 bv4 = *(const float4*)&Bs[bf][kk][tx * 4];
            float av[4] = {a.x, a.y, a.z, a.w};
            float bv[4] = {bv4.x, bv4.y, bv4.z, bv4.w};
#pragma unroll
            for (int i = 0; i < 4; i++)
#pragma unroll
                for (int j = 0; j < 4; j++) acc[i][j] += av[i] * bv[j];
        }
        if (kt + 1 < nk) {
            int nb = (kt + 1) & 1;
            if (isA) {
                As[nb][ak + 0][ar] = aReg.x; As[nb][ak + 1][ar] = aReg.y;
                As[nb][ak + 2][ar] = aReg.z; As[nb][ak + 3][ar] = aReg.w;
            } else {
                *(float4*)&Bs[nb][bk][bn] = bReg;
            }
            __syncthreads();
        }
    }

    int d = (n0 >> 2) + tx;
#pragma unroll
    for (int i = 0; i < 4; i++) {
        int row = m0 + ty * 4 + i;
        float4 g4 = *(const float4*)&XGp[((size_t)row * TT + t) * NG + 4 * d];
        float iv = acc[i][0] + g4.x;
        float fv = acc[i][1] + g4.y;
        float cg = acc[i][2] + g4.z;
        float ov = acc[i][3] + g4.w;
        float cp = c[row * DD + d];
        float cn = sigmoidf_(fv) * cp + sigmoidf_(iv) * tanhf(cg);
        float hn = sigmoidf_(ov) * tanhf(cn);
        c[row * DD + d] = cn;
        hout[row * DD + d] = hn;
        sent[row * DD + d] += hn;
    }
}

// ---------------- GEMM: 64x64x8, flexible epilogue (heads / classifier) -------------
__global__ __launch_bounds__(256) void sgemm64(
    const float* __restrict__ A, const float* __restrict__ B, float* __restrict__ C,
    int M, int N, int K,
    const float* __restrict__ bias, float biasScale, int act)
{
    __shared__ float As[8][64];
    __shared__ float Bs[8][64];
    int tid = threadIdx.x;
    int m0 = blockIdx.y * 64;
    int n0 = blockIdx.x * 64;
    int tx = tid & 15, ty = tid >> 4;

    bool isA = tid < 128;
    int ar = tid >> 1;
    int ak = (tid & 1) * 4;
    int u  = tid - 128;
    int bk = u >> 4;
    int bn = (u & 15) * 4;

    const float* Aptr = A + (size_t)(m0 + (isA ? ar : 0)) * K + (isA ? ak : 0);
    int bcol = n0 + bn;
    const float* Bptr = B + (size_t)bk * N + bcol;

    float4 aReg = make_float4(0.f, 0.f, 0.f, 0.f);
    float4 bReg = make_float4(0.f, 0.f, 0.f, 0.f);
    if (isA) aReg = *(const float4*)Aptr;
    else {
        if (bcol + 3 < N) bReg = *(const float4*)Bptr;
        else {
            bReg.x = (bcol + 0 < N) ? Bptr[0] : 0.f;
            bReg.y = (bcol + 1 < N) ? Bptr[1] : 0.f;
            bReg.z = (bcol + 2 < N) ? Bptr[2] : 0.f;
            bReg.w = (bcol + 3 < N) ? Bptr[3] : 0.f;
        }
    }

    float acc[4][4];
#pragma unroll
    for (int i = 0; i < 4; i++)
#pragma unroll
        for (int j = 0; j < 4; j++) acc[i][j] = 0.f;

    int nk = K >> 3;
    for (int kt = 0; kt < nk; ++kt) {
        if (isA) {
            As[ak + 0][ar] = aReg.x; As[ak + 1][ar] = aReg.y;
            As[ak + 2][ar] = aReg.z; As[ak + 3][ar] = aReg.w;
        } else {
            *(float4*)&Bs[bk][bn] = bReg;
        }
        __syncthreads();
        if (kt + 1 < nk) {
            if (isA) aReg = *(const float4*)(Aptr + (kt + 1) * 8);
            else {
                const float* bp2 = Bptr + (size_t)(kt + 1) * 8 * N;
                if (bcol + 3 < N) bReg = *(const float4*)bp2;
                else {
                    bReg.x = (bcol + 0 < N) ? bp2[0] : 0.f;
                    bReg.y = (bcol + 1 < N) ? bp2[1] : 0.f;
                    bReg.z = (bcol + 2 < N) ? bp2[2] : 0.f;
                    bReg.w = (bcol + 3 < N) ? bp2[3] : 0.f;
                }
            }
        }
#pragma unroll
        for (int kk = 0; kk < 8; ++kk) {
            float4 a = *(const float4*)&As[kk][ty * 4];
            float4 bv4 = *(const float4*)&Bs[kk][tx * 4];
            float av[4] = {a.x, a.y, a.z, a.w};
            float bv[4] = {bv4.x, bv4.y, bv4.z, bv4.w};
#pragma unroll
            for (int i = 0; i < 4; i++)
#pragma unroll
                for (int j = 0; j < 4; j++) acc[i][j] += av[i] * bv[j];
        }
        __syncthreads();
    }

#pragma unroll
    for (int i = 0; i < 4; i++) {
        int row = m0 + ty * 4 + i;
#pragma unroll
        for (int j = 0; j < 4; j++) {
            int col = n0 + tx * 4 + j;
            if (col >= N) continue;
            float v = acc[i][j];
            if (bias) v += bias[col] * biasScale;
            if (act)  v = tanhf(v);
            C[(size_t)row * N + col] = v;
        }
    }
}

// ---------------- launch ----------------
extern "C" void kernel_launch(void* const* d_in, const int* in_sizes, int n_in,
                              void* d_out, int out_size) {
    const float* image_feat = (const float*)d_in[0];
    const int*   qenc       = (const int*)d_in[1];
    const float* W_ip   = (const float*)d_in[2];
    const float* b_ip   = (const float*)d_in[3];
    const float* emb    = (const float*)d_in[4];
    const float* W_uni  = (const float*)d_in[5];
    const float* b_uni  = (const float*)d_in[6];
    const float* W_bi   = (const float*)d_in[7];
    const float* b_bi   = (const float*)d_in[8];
    const float* W_tri  = (const float*)d_in[9];
    const float* b_tri  = (const float*)d_in[10];
    const float* Wx     = (const float*)d_in[11];
    const float* Wh     = (const float*)d_in[12];
    const float* b_lstm = (const float*)d_in[13];
    // d_in[14..23]: affinity/attention weights — dead (softmax over 1 logit == 1)
    const float* W_w    = (const float*)d_in[24];
    const float* b_w    = (const float*)d_in[25];
    const float* W_p    = (const float*)d_in[26];
    const float* b_p    = (const float*)d_in[27];
    const float* W_s    = (const float*)d_in[28];
    const float* b_s    = (const float*)d_in[29];
    const float* W_f    = (const float*)d_in[30];
    const float* b_f    = (const float*)d_in[31];
    float* out = (float*)d_out;

    cudaFuncSetAttribute(mma_gemm, cudaFuncAttributeMaxDynamicSharedMemorySize, MMA_SMEM_BYTES);

    float* S = nullptr;
    cudaGetSymbolAddress((void**)&S, g_scratch);
    __nv_bfloat16 *Xhi, *Xlo, *Phi, *Plo, *WcTh, *WcTl, *WxTh, *WxTl;
    cudaGetSymbolAddress((void**)&Xhi,  g_Xhi);
    cudaGetSymbolAddress((void**)&Xlo,  g_Xlo);
    cudaGetSymbolAddress((void**)&Phi,  g_Phi);
    cudaGetSymbolAddress((void**)&Plo,  g_Plo);
    cudaGetSymbolAddress((void**)&WcTh, g_WcT_hi);
    cudaGetSymbolAddress((void**)&WcTl, g_WcT_lo);
    cudaGetSymbolAddress((void**)&WxTh, g_WxT_hi);
    cudaGetSymbolAddress((void**)&WxTl, g_WxT_lo);

    float* Simg      = S + O_SIMG;
    float* imgsum    = S + O_IMGSUM;
    float* X         = S + O_X;
    float* wordsum   = S + O_WORDSUM;
    float* Y         = S + O_Y;
    float* phrase    = S + O_PHRASE;
    float* phrasesum = S + O_PHRASESUM;
    float* Whp       = S + O_WHP;
    float* bp        = S + O_BP;
    float* XGp       = S + O_XG;
    float* h0        = S + O_H0;
    float* h1        = S + O_H1;
    float* c         = S + O_C;
    float* sentsum   = S + O_SENT;
    float* v1        = S + O_V1;
    float* hw        = S + O_HW;
    float* cat       = S + O_CAT;
    float* hp        = S + O_HP;
    float* hs        = S + O_HS;

    // image path
    reduce_img<<<BSZ, DD>>>(image_feat, Simg);
    sgemm64<<<dim3(8, 4), 256>>>(Simg, W_ip, imgsum, 256, 512, 512, b_ip, (float)RR, 0);

    // weight prep (transposed + bf16 split for mma; fp32 permute for LSTM recurrent)
    build_wcombT<<<(NY * 512) / 256, 256>>>(W_uni, W_bi, W_tri, WcTh, WcTl);
    build_wxT<<<(NG * 512) / 256, 256>>>(Wx, WxTh, WxTl);
    permute_gates<<<(512 * NG) / 256, 256>>>(Wh, Whp);
    permute_bias<<<NG / 256, 256>>>(b_lstm, bp);

    // word path
    gather_word<<<BT, DD>>>(qenc, emb, X);
    reduce26<<<BSZ, DD>>>(X, wordsum);
    split2<<<(BT * DD) / 256, 256>>>(X, Xhi, Xlo);

    // phrase: tensor-core GEMM [6656 x 3584] then shifted combine
    mma_gemm<<<dim3(NY / 128, BT / 128), 256, MMA_SMEM_BYTES>>>(
        Xhi, Xlo, WcTh, WcTl, Y, NY, nullptr);
    combine_phrase<<<BT, DD>>>(Y, b_uni, b_bi, b_tri, phrase);
    reduce26<<<BSZ, DD>>>(phrase, phrasesum);
    split2<<<(BT * DD) / 256, 256>>>(phrase, Phi, Plo);

    // LSTM: tensor-core pre-GEMM [6656 x 2048] + bias, then 26 fused recurrent steps
    mma_gemm<<<dim3(NG / 128, BT / 128), 256, MMA_SMEM_BYTES>>>(
        Phi, Plo, WxTh, WxTl, XGp, NG, bp);
    lstm0<<<BSZ, DD>>>(XGp, h0, c, sentsum);
    for (int t = 1; t < TT; ++t) {
        const float* hin = (t & 1) ? h0 : h1;
        float*       ho  = (t & 1) ? h1 : h0;
        lstm_step<<<dim3(32, 4), 256>>>(hin, Whp, XGp, t, ho, c, sentsum);
    }

    // heads
    ew_add<<<(BSZ * DD) / 256, 256>>>(imgsum, wordsum, v1);
    sgemm64<<<dim3(8, 4), 256>>>(v1, W_w, hw, 256, 512, 512, b_w, 1.f, 1);
    ew_cat<<<BSZ, DD>>>(imgsum, phrasesum, hw, cat);
    sgemm64<<<dim3(8, 4), 256>>>(cat, W_p, hp, 256, 512, 1024, b_p, 1.f, 1);
    ew_cat<<<BSZ, DD>>>(imgsum, sentsum, hp, cat);
    sgemm64<<<dim3(8, 4), 256>>>(cat, W_s, hs, 256, 512, 1024, b_s, 1.f, 1);

    // final classifier
    sgemm64<<<dim3((AVN + 63) / 64, 4), 256>>>(hs, W_f, out, 256, AVN, 512, b_f, 1.f, 0);
}